// round 13
// baseline (speedup 1.0000x reference)
#include <cuda_runtime.h>
#include <cstdint>
#include <math.h>

// ---------------------------------------------------------------------------
// A : cp.async staging (32 img/block, 2048 blocks, 2 commit groups) + pool +
//     circuit closed form + per-block partial stats. PDL trigger at end.
// SC: one fused kernel (grid 257). Block 256 reduces partials -> g_sb and
//     release-publishes a flag; blocks 0..255 preload out, acquire-spin,
//     normalize, store. Flag/done self-reset for graph replay.
// ---------------------------------------------------------------------------

#define B_TOTAL 65536
#define IPB     32
#define NB      (B_TOTAL / IPB)         // 2048 blocks
#define THREADS 256
#define SROW    148
#define NCONS   256                     // consumer blocks in SC

__device__ __align__(16) float g_part[NB * 8];
__device__ __align__(16) float g_sb[8];
__device__ unsigned g_flag = 0;
__device__ unsigned g_done = 0;

__device__ __forceinline__ void cp16(unsigned int saddr, const float4* gptr) {
    asm volatile("cp.async.cg.shared.global [%0], [%1], 16;" :: "r"(saddr), "l"(gptr));
}
__device__ __forceinline__ void pdl_trigger() {
    asm volatile("griddepcontrol.launch_dependents;" ::: "memory");
}
__device__ __forceinline__ void pdl_wait() {
    asm volatile("griddepcontrol.wait;" ::: "memory");
}

__global__ __launch_bounds__(THREADS)
void qfc_kernelA(const float* __restrict__ x,
                 const float* __restrict__ pr,
                 float* __restrict__ out)
{
    __shared__ __align__(16) float sd[IPB][SROW];
    __shared__ float sz[IPB][4];

    const int tid = threadIdx.x;
    const float4* __restrict__ x4 = (const float4*)x;
    const long ib = (long)blockIdx.x * IPB;

    // ---- stage: two commit groups of 16 images (576 float4 each) ----------
#pragma unroll
    for (int h = 0; h < 2; h++) {
#pragma unroll
        for (int it = 0; it < 3; it++) {
            int i = tid + it * THREADS;
            if (i < 16 * 36) {
                int img = (i / 36) + h * 16;
                int p   = i % 36;
                unsigned int sa = (unsigned int)__cvta_generic_to_shared(&sd[img][p * 4]);
                cp16(sa, &x4[(ib + img) * 144 + p]);
            }
        }
        asm volatile("cp.async.commit_group;");
    }

    const int g = tid & 3;
    const float phi  = pr[g * 2 + 0];
    const float lam  = pr[g * 2 + 1];
    const float clam = __cosf(lam);
    const float k2   = __sinf(lam) * __sinf(phi);

    // ---- group 0 ready: pool images 0-15 while group 1 lands --------------
    asm volatile("cp.async.wait_group 1;");
    __syncthreads();
    if (tid < 64) {
        const int img = tid >> 2;
        const float* row = &sd[img][g * 6];
        float a0 = 0.f, a1 = 0.f, a2 = 0.f, a3 = 0.f;
#pragma unroll
        for (int r = 0; r < 6; r++) {
            a0 += row[r * 24 + 0];
            a1 += row[r * 24 + 1];
            a2 += row[r * 24 + 2];
            a3 += row[r * 24 + 3];
            a0 += row[r * 24 + 4];
            a1 += row[r * 24 + 5];
        }
        const float theta = ((a0 + a1) + (a2 + a3)) * (1.f / 36.f);
        float st, ct;
        __sincosf(theta, &st, &ct);
        sz[img][g] = clam * ct + k2 * st;
    }

    // ---- group 1 ready: pool images 16-31 ---------------------------------
    asm volatile("cp.async.wait_group 0;");
    __syncthreads();
    if (tid >= 64 && tid < 128) {
        const int img = tid >> 2;
        const float* row = &sd[img][g * 6];
        float a0 = 0.f, a1 = 0.f, a2 = 0.f, a3 = 0.f;
#pragma unroll
        for (int r = 0; r < 6; r++) {
            a0 += row[r * 24 + 0];
            a1 += row[r * 24 + 1];
            a2 += row[r * 24 + 2];
            a3 += row[r * 24 + 3];
            a0 += row[r * 24 + 4];
            a1 += row[r * 24 + 5];
        }
        const float theta = ((a0 + a1) + (a2 + a3)) * (1.f / 36.f);
        float st, ct;
        __sincosf(theta, &st, &ct);
        sz[img][g] = clam * ct + k2 * st;
    }
    __syncthreads();

    // ---- products + raw out write + deterministic warp-0 reduction --------
    if (tid < 32) {
        float4 zz = *(float4*)&sz[tid][0];
        float o0 = zz.x;
        float o1 = o0 * zz.y;
        float o2 = o1 * zz.z;
        float o3 = o2 * zz.w;
        ((float4*)out)[ib + tid] = make_float4(o0, o1, o2, o3);

        float acc[8] = {o0, o1, o2, o3, o0 * o0, o1 * o1, o2 * o2, o3 * o3};
#pragma unroll
        for (int k = 0; k < 8; k++) {
#pragma unroll
            for (int off = 16; off; off >>= 1)
                acc[k] += __shfl_down_sync(0xffffffffu, acc[k], off);
        }
        if (tid == 0) {
            *(float4*)&g_part[blockIdx.x * 8]     = make_float4(acc[0], acc[1], acc[2], acc[3]);
            *(float4*)&g_part[blockIdx.x * 8 + 4] = make_float4(acc[4], acc[5], acc[6], acc[7]);
        }
    }
    pdl_trigger();
}

// ---- SC: fused stats + normalize -------------------------------------------
__global__ __launch_bounds__(256)
void qfc_kernelSC(const float* __restrict__ gamma,
                  const float* __restrict__ beta,
                  float* __restrict__ out)
{
    const int tid = threadIdx.x;

    pdl_wait();   // A's writes (out raw, g_part) visible after this

    if (blockIdx.x == NCONS) {
        // ---------------- producer: stats finalize -> g_sb, publish --------
        __shared__ float swarp[8][8];
        const int wrp  = tid >> 5;
        const int lane = tid & 31;

        const float4* __restrict__ p4 = (const float4*)g_part;   // 4096 float4
        float r[8] = {0.f, 0.f, 0.f, 0.f, 0.f, 0.f, 0.f, 0.f};
#pragma unroll
        for (int it = 0; it < NB / 256; it++) {                   // 8 iters
            int j = tid + it * 256;
            float4 s  = __ldcg(&p4[j * 2]);
            float4 qq = __ldcg(&p4[j * 2 + 1]);
            r[0] += s.x;  r[1] += s.y;  r[2] += s.z;  r[3] += s.w;
            r[4] += qq.x; r[5] += qq.y; r[6] += qq.z; r[7] += qq.w;
        }
#pragma unroll
        for (int k = 0; k < 8; k++) {
#pragma unroll
            for (int off = 16; off; off >>= 1)
                r[k] += __shfl_down_sync(0xffffffffu, r[k], off);
        }
        if (lane == 0) {
#pragma unroll
            for (int k = 0; k < 8; k++) swarp[wrp][k] = r[k];
        }
        __syncthreads();

        if (tid < 4) {
            float ss = 0.f, qq = 0.f;
#pragma unroll
            for (int w = 0; w < 8; w++) { ss += swarp[w][tid]; qq += swarp[w][4 + tid]; }
            const float mean = ss * (1.f / (float)B_TOTAL);
            const float ex2  = qq * (1.f / (float)B_TOTAL);
            const float var  = fmaxf(ex2 - mean * mean, 0.f);
            const float inv  = rsqrtf(var + 1e-5f);
            const float sc   = gamma[tid] * inv;
            g_sb[tid]     = sc;
            g_sb[4 + tid] = beta[tid] - mean * sc;
        }
        __syncthreads();
        if (tid == 0) {
            __threadfence();                                    // publish g_sb
            asm volatile("st.release.gpu.global.u32 [%0], %1;"
                         :: "l"(&g_flag), "r"(1u) : "memory");
        }
    } else {
        // ---------------- consumer: preload, spin, normalize, store --------
        const int i = blockIdx.x * 256 + tid;
        float4 v = __ldcg(&((const float4*)out)[i]);            // hide under spin

        if (tid == 0) {
            unsigned f;
            do {
                asm volatile("ld.acquire.gpu.global.u32 %0, [%1];"
                             : "=r"(f) : "l"(&g_flag) : "memory");
            } while (!f);
        }
        __syncthreads();

        const float4 scv = __ldcg((const float4*)&g_sb[0]);
        const float4 biv = __ldcg((const float4*)&g_sb[4]);
        v.x = v.x * scv.x + biv.x;
        v.y = v.y * scv.y + biv.y;
        v.z = v.z * scv.z + biv.z;
        v.w = v.w * scv.w + biv.w;
        ((float4*)out)[i] = v;

        // self-reset for graph replay: last consumer clears flag+counter
        if (tid == 0) {
            unsigned d = atomicAdd(&g_done, 1);
            if (d == NCONS - 1) {
                g_done = 0;
                asm volatile("st.relaxed.gpu.global.u32 [%0], %1;"
                             :: "l"(&g_flag), "r"(0u) : "memory");
            }
        }
    }
}

extern "C" void kernel_launch(void* const* d_in, const int* in_sizes, int n_in,
                              void* d_out, int out_size)
{
    const float* x      = (const float*)d_in[0];   // [65536,1,24,24]
    const float* params = (const float*)d_in[1];   // [4,2]
    const float* gamma  = (const float*)d_in[2];   // [4]
    const float* beta   = (const float*)d_in[3];   // [4]
    float* out = (float*)d_out;                    // [65536,4]

    qfc_kernelA<<<NB, THREADS>>>(x, params, out);

    cudaLaunchAttribute attr;
    attr.id = cudaLaunchAttributeProgrammaticStreamSerialization;
    attr.val.programmaticStreamSerializationAllowed = 1;

    cudaLaunchConfig_t cfg = {};
    cfg.gridDim  = dim3(NCONS + 1, 1, 1);
    cfg.blockDim = dim3(256, 1, 1);
    cfg.attrs    = &attr;
    cfg.numAttrs = 1;
    cudaLaunchKernelEx(&cfg, qfc_kernelSC, gamma, beta, out);
}

// round 14
// speedup vs baseline: 1.1198x; 1.1198x over previous
#include <cuda_runtime.h>
#include <cstdint>
#include <math.h>

// ---------------------------------------------------------------------------
// A : cp.async staging (32 img/block, 2048 blocks, 128 threads, 2 commit
//     groups) + pool + circuit closed form + per-block partial stats.
// S : 1-block stats finalize -> g_sb (PDL: overlaps A's tail; 1 block only).
// C : pure normalize, 1 float4/thread (plain launch).
// ---------------------------------------------------------------------------

#define B_TOTAL 65536
#define IPB     32
#define NB      (B_TOTAL / IPB)         // 2048 blocks
#define THREADS 128
#define SROW    148

__device__ __align__(16) float g_part[NB * 8];  // per-block [sum0..3, sumsq0..3]
__device__ __align__(16) float g_sb[8];         // scale[4], bias[4]

__device__ __forceinline__ void cp16(unsigned int saddr, const float4* gptr) {
    asm volatile("cp.async.cg.shared.global [%0], [%1], 16;" :: "r"(saddr), "l"(gptr));
}
__device__ __forceinline__ void pdl_trigger() {
    asm volatile("griddepcontrol.launch_dependents;" ::: "memory");
}
__device__ __forceinline__ void pdl_wait() {
    asm volatile("griddepcontrol.wait;" ::: "memory");
}

__global__ __launch_bounds__(THREADS)
void qfc_kernelA(const float* __restrict__ x,
                 const float* __restrict__ pr,
                 float* __restrict__ out)
{
    __shared__ __align__(16) float sd[IPB][SROW];
    __shared__ float sz[IPB][4];

    const int tid = threadIdx.x;
    const float4* __restrict__ x4 = (const float4*)x;
    const long ib = (long)blockIdx.x * IPB;

    // ---- stage: two commit groups of 16 images (576 float4 each) ----------
#pragma unroll
    for (int h = 0; h < 2; h++) {
#pragma unroll
        for (int it = 0; it < 5; it++) {
            int i = tid + it * THREADS;
            if (i < 16 * 36) {
                int img = (i / 36) + h * 16;
                int p   = i % 36;
                unsigned int sa = (unsigned int)__cvta_generic_to_shared(&sd[img][p * 4]);
                cp16(sa, &x4[(ib + img) * 144 + p]);
            }
        }
        asm volatile("cp.async.commit_group;");
    }

    const int g = tid & 3;
    const float phi  = pr[g * 2 + 0];
    const float lam  = pr[g * 2 + 1];
    const float clam = __cosf(lam);
    const float k2   = __sinf(lam) * __sinf(phi);

    // ---- group 0 ready: pool images 0-15 while group 1 lands --------------
    asm volatile("cp.async.wait_group 1;");
    __syncthreads();
    if (tid < 64) {
        const int img = tid >> 2;                 // 0..15
        const float* row = &sd[img][g * 6];
        float a0 = 0.f, a1 = 0.f, a2 = 0.f, a3 = 0.f;
#pragma unroll
        for (int r = 0; r < 6; r++) {
            a0 += row[r * 24 + 0];
            a1 += row[r * 24 + 1];
            a2 += row[r * 24 + 2];
            a3 += row[r * 24 + 3];
            a0 += row[r * 24 + 4];
            a1 += row[r * 24 + 5];
        }
        const float theta = ((a0 + a1) + (a2 + a3)) * (1.f / 36.f);
        float st, ct;
        __sincosf(theta, &st, &ct);
        sz[img][g] = clam * ct + k2 * st;
    }

    // ---- group 1 ready: pool images 16-31 ---------------------------------
    asm volatile("cp.async.wait_group 0;");
    __syncthreads();
    if (tid >= 64) {
        const int img = tid >> 2;                 // 16..31
        const float* row = &sd[img][g * 6];
        float a0 = 0.f, a1 = 0.f, a2 = 0.f, a3 = 0.f;
#pragma unroll
        for (int r = 0; r < 6; r++) {
            a0 += row[r * 24 + 0];
            a1 += row[r * 24 + 1];
            a2 += row[r * 24 + 2];
            a3 += row[r * 24 + 3];
            a0 += row[r * 24 + 4];
            a1 += row[r * 24 + 5];
        }
        const float theta = ((a0 + a1) + (a2 + a3)) * (1.f / 36.f);
        float st, ct;
        __sincosf(theta, &st, &ct);
        sz[img][g] = clam * ct + k2 * st;
    }
    __syncthreads();

    // ---- products + raw out write + deterministic warp-0 reduction --------
    if (tid < 32) {
        float4 zz = *(float4*)&sz[tid][0];
        float o0 = zz.x;
        float o1 = o0 * zz.y;
        float o2 = o1 * zz.z;
        float o3 = o2 * zz.w;
        ((float4*)out)[ib + tid] = make_float4(o0, o1, o2, o3);

        float acc[8] = {o0, o1, o2, o3, o0 * o0, o1 * o1, o2 * o2, o3 * o3};
#pragma unroll
        for (int k = 0; k < 8; k++) {
#pragma unroll
            for (int off = 16; off; off >>= 1)
                acc[k] += __shfl_down_sync(0xffffffffu, acc[k], off);
        }
        if (tid == 0) {
            *(float4*)&g_part[blockIdx.x * 8]     = make_float4(acc[0], acc[1], acc[2], acc[3]);
            *(float4*)&g_part[blockIdx.x * 8 + 4] = make_float4(acc[4], acc[5], acc[6], acc[7]);
        }
    }
    pdl_trigger();
}

// ---- S: single-block stats finalize -> g_sb (PDL, 1 block) -----------------
__global__ __launch_bounds__(256)
void qfc_kernelS(const float* __restrict__ gamma,
                 const float* __restrict__ beta)
{
    __shared__ float swarp[8][8];
    const int tid  = threadIdx.x;
    const int wrp  = tid >> 5;
    const int lane = tid & 31;

    pdl_wait();   // A's g_part writes visible after this

    const float4* __restrict__ p4 = (const float4*)g_part;   // 4096 float4
    float r[8] = {0.f, 0.f, 0.f, 0.f, 0.f, 0.f, 0.f, 0.f};
#pragma unroll
    for (int it = 0; it < NB / 256; it++) {                   // 8 iters
        int j = tid + it * 256;
        float4 s  = __ldcg(&p4[j * 2]);
        float4 qq = __ldcg(&p4[j * 2 + 1]);
        r[0] += s.x;  r[1] += s.y;  r[2] += s.z;  r[3] += s.w;
        r[4] += qq.x; r[5] += qq.y; r[6] += qq.z; r[7] += qq.w;
    }
#pragma unroll
    for (int k = 0; k < 8; k++) {
#pragma unroll
        for (int off = 16; off; off >>= 1)
            r[k] += __shfl_down_sync(0xffffffffu, r[k], off);
    }
    if (lane == 0) {
#pragma unroll
        for (int k = 0; k < 8; k++) swarp[wrp][k] = r[k];
    }
    __syncthreads();

    if (tid < 4) {
        float ss = 0.f, qq = 0.f;
#pragma unroll
        for (int w = 0; w < 8; w++) { ss += swarp[w][tid]; qq += swarp[w][4 + tid]; }
        const float mean = ss * (1.f / (float)B_TOTAL);
        const float ex2  = qq * (1.f / (float)B_TOTAL);
        const float var  = fmaxf(ex2 - mean * mean, 0.f);
        const float inv  = rsqrtf(var + 1e-5f);
        const float sc   = gamma[tid] * inv;
        g_sb[tid]     = sc;
        g_sb[4 + tid] = beta[tid] - mean * sc;
    }
}

// ---- C: pure normalize, 1 float4 per thread --------------------------------
__global__ __launch_bounds__(256)
void qfc_kernelC(float* __restrict__ out)
{
    const float4 scv = *(const float4*)&g_sb[0];
    const float4 biv = *(const float4*)&g_sb[4];
    const int i = blockIdx.x * 256 + threadIdx.x;    // 65536 threads total
    float4 v = ((float4*)out)[i];
    v.x = v.x * scv.x + biv.x;
    v.y = v.y * scv.y + biv.y;
    v.z = v.z * scv.z + biv.z;
    v.w = v.w * scv.w + biv.w;
    ((float4*)out)[i] = v;
}

extern "C" void kernel_launch(void* const* d_in, const int* in_sizes, int n_in,
                              void* d_out, int out_size)
{
    const float* x      = (const float*)d_in[0];   // [65536,1,24,24]
    const float* params = (const float*)d_in[1];   // [4,2]
    const float* gamma  = (const float*)d_in[2];   // [4]
    const float* beta   = (const float*)d_in[3];   // [4]
    float* out = (float*)d_out;                    // [65536,4]

    qfc_kernelA<<<NB, THREADS>>>(x, params, out);

    cudaLaunchAttribute attr;
    attr.id = cudaLaunchAttributeProgrammaticStreamSerialization;
    attr.val.programmaticStreamSerializationAllowed = 1;

    cudaLaunchConfig_t cfgS = {};
    cfgS.gridDim  = dim3(1, 1, 1);
    cfgS.blockDim = dim3(256, 1, 1);
    cfgS.attrs    = &attr;
    cfgS.numAttrs = 1;
    cudaLaunchKernelEx(&cfgS, qfc_kernelS, gamma, beta);

    qfc_kernelC<<<B_TOTAL / 256, 256>>>(out);
}

// round 15
// speedup vs baseline: 1.1297x; 1.0088x over previous
#include <cuda_runtime.h>
#include <cstdint>
#include <math.h>

// ---------------------------------------------------------------------------
// A : cp.async staging (32 img/block, 2048 blocks, 128 threads, 2 commit
//     groups) + pool + circuit closed form + per-block partial stats. [11.55us]
// S : 1-block stats finalize -> g_sb (plain launch).
// C : pure normalize, 1 float4/thread (plain launch).   [S+C tail: 1.86us]
// ---------------------------------------------------------------------------

#define B_TOTAL 65536
#define IPB     32
#define NB      (B_TOTAL / IPB)         // 2048 blocks
#define THREADS 128
#define SROW    148

__device__ __align__(16) float g_part[NB * 8];  // per-block [sum0..3, sumsq0..3]
__device__ __align__(16) float g_sb[8];         // scale[4], bias[4]

__device__ __forceinline__ void cp16(unsigned int saddr, const float4* gptr) {
    asm volatile("cp.async.cg.shared.global [%0], [%1], 16;" :: "r"(saddr), "l"(gptr));
}

__global__ __launch_bounds__(THREADS)
void qfc_kernelA(const float* __restrict__ x,
                 const float* __restrict__ pr,
                 float* __restrict__ out)
{
    __shared__ __align__(16) float sd[IPB][SROW];
    __shared__ float sz[IPB][4];

    const int tid = threadIdx.x;
    const float4* __restrict__ x4 = (const float4*)x;
    const long ib = (long)blockIdx.x * IPB;

    // ---- stage: two commit groups of 16 images (576 float4 each) ----------
#pragma unroll
    for (int h = 0; h < 2; h++) {
#pragma unroll
        for (int it = 0; it < 5; it++) {
            int i = tid + it * THREADS;
            if (i < 16 * 36) {
                int img = (i / 36) + h * 16;
                int p   = i % 36;
                unsigned int sa = (unsigned int)__cvta_generic_to_shared(&sd[img][p * 4]);
                cp16(sa, &x4[(ib + img) * 144 + p]);
            }
        }
        asm volatile("cp.async.commit_group;");
    }

    const int g = tid & 3;
    const float phi  = pr[g * 2 + 0];
    const float lam  = pr[g * 2 + 1];
    const float clam = __cosf(lam);
    const float k2   = __sinf(lam) * __sinf(phi);

    // ---- group 0 ready: pool images 0-15 while group 1 lands --------------
    asm volatile("cp.async.wait_group 1;");
    __syncthreads();
    if (tid < 64) {
        const int img = tid >> 2;                 // 0..15
        const float* row = &sd[img][g * 6];
        float a0 = 0.f, a1 = 0.f, a2 = 0.f, a3 = 0.f;
#pragma unroll
        for (int r = 0; r < 6; r++) {
            a0 += row[r * 24 + 0];
            a1 += row[r * 24 + 1];
            a2 += row[r * 24 + 2];
            a3 += row[r * 24 + 3];
            a0 += row[r * 24 + 4];
            a1 += row[r * 24 + 5];
        }
        const float theta = ((a0 + a1) + (a2 + a3)) * (1.f / 36.f);
        float st, ct;
        __sincosf(theta, &st, &ct);
        sz[img][g] = clam * ct + k2 * st;
    }

    // ---- group 1 ready: pool images 16-31 ---------------------------------
    asm volatile("cp.async.wait_group 0;");
    __syncthreads();
    if (tid >= 64) {
        const int img = tid >> 2;                 // 16..31
        const float* row = &sd[img][g * 6];
        float a0 = 0.f, a1 = 0.f, a2 = 0.f, a3 = 0.f;
#pragma unroll
        for (int r = 0; r < 6; r++) {
            a0 += row[r * 24 + 0];
            a1 += row[r * 24 + 1];
            a2 += row[r * 24 + 2];
            a3 += row[r * 24 + 3];
            a0 += row[r * 24 + 4];
            a1 += row[r * 24 + 5];
        }
        const float theta = ((a0 + a1) + (a2 + a3)) * (1.f / 36.f);
        float st, ct;
        __sincosf(theta, &st, &ct);
        sz[img][g] = clam * ct + k2 * st;
    }
    __syncthreads();

    // ---- products + raw out write + deterministic warp-0 reduction --------
    if (tid < 32) {
        float4 zz = *(float4*)&sz[tid][0];
        float o0 = zz.x;
        float o1 = o0 * zz.y;
        float o2 = o1 * zz.z;
        float o3 = o2 * zz.w;
        ((float4*)out)[ib + tid] = make_float4(o0, o1, o2, o3);

        float acc[8] = {o0, o1, o2, o3, o0 * o0, o1 * o1, o2 * o2, o3 * o3};
#pragma unroll
        for (int k = 0; k < 8; k++) {
#pragma unroll
            for (int off = 16; off; off >>= 1)
                acc[k] += __shfl_down_sync(0xffffffffu, acc[k], off);
        }
        if (tid == 0) {
            *(float4*)&g_part[blockIdx.x * 8]     = make_float4(acc[0], acc[1], acc[2], acc[3]);
            *(float4*)&g_part[blockIdx.x * 8 + 4] = make_float4(acc[4], acc[5], acc[6], acc[7]);
        }
    }
}

// ---- S: single-block stats finalize -> g_sb --------------------------------
__global__ __launch_bounds__(256)
void qfc_kernelS(const float* __restrict__ gamma,
                 const float* __restrict__ beta)
{
    __shared__ float swarp[8][8];
    const int tid  = threadIdx.x;
    const int wrp  = tid >> 5;
    const int lane = tid & 31;

    const float4* __restrict__ p4 = (const float4*)g_part;   // 4096 float4
    float r[8] = {0.f, 0.f, 0.f, 0.f, 0.f, 0.f, 0.f, 0.f};
#pragma unroll
    for (int it = 0; it < NB / 256; it++) {                   // 8 iters
        int j = tid + it * 256;
        float4 s  = __ldcg(&p4[j * 2]);
        float4 qq = __ldcg(&p4[j * 2 + 1]);
        r[0] += s.x;  r[1] += s.y;  r[2] += s.z;  r[3] += s.w;
        r[4] += qq.x; r[5] += qq.y; r[6] += qq.z; r[7] += qq.w;
    }
#pragma unroll
    for (int k = 0; k < 8; k++) {
#pragma unroll
        for (int off = 16; off; off >>= 1)
            r[k] += __shfl_down_sync(0xffffffffu, r[k], off);
    }
    if (lane == 0) {
#pragma unroll
        for (int k = 0; k < 8; k++) swarp[wrp][k] = r[k];
    }
    __syncthreads();

    if (tid < 4) {
        float ss = 0.f, qq = 0.f;
#pragma unroll
        for (int w = 0; w < 8; w++) { ss += swarp[w][tid]; qq += swarp[w][4 + tid]; }
        const float mean = ss * (1.f / (float)B_TOTAL);
        const float ex2  = qq * (1.f / (float)B_TOTAL);
        const float var  = fmaxf(ex2 - mean * mean, 0.f);
        const float inv  = rsqrtf(var + 1e-5f);
        const float sc   = gamma[tid] * inv;
        g_sb[tid]     = sc;
        g_sb[4 + tid] = beta[tid] - mean * sc;
    }
}

// ---- C: pure normalize, 1 float4 per thread --------------------------------
__global__ __launch_bounds__(256)
void qfc_kernelC(float* __restrict__ out)
{
    const float4 scv = *(const float4*)&g_sb[0];
    const float4 biv = *(const float4*)&g_sb[4];
    const int i = blockIdx.x * 256 + threadIdx.x;    // 65536 threads total
    float4 v = ((float4*)out)[i];
    v.x = v.x * scv.x + biv.x;
    v.y = v.y * scv.y + biv.y;
    v.z = v.z * scv.z + biv.z;
    v.w = v.w * scv.w + biv.w;
    ((float4*)out)[i] = v;
}

extern "C" void kernel_launch(void* const* d_in, const int* in_sizes, int n_in,
                              void* d_out, int out_size)
{
    const float* x      = (const float*)d_in[0];   // [65536,1,24,24]
    const float* params = (const float*)d_in[1];   // [4,2]
    const float* gamma  = (const float*)d_in[2];   // [4]
    const float* beta   = (const float*)d_in[3];   // [4]
    float* out = (float*)d_out;                    // [65536,4]

    qfc_kernelA<<<NB, THREADS>>>(x, params, out);
    qfc_kernelS<<<1, 256>>>(gamma, beta);
    qfc_kernelC<<<B_TOTAL / 256, 256>>>(out);
}

// round 16
// speedup vs baseline: 1.2882x; 1.1404x over previous
#include <cuda_runtime.h>
#include <cuda.h>
#include <cstdint>
#include <math.h>

// ---------------------------------------------------------------------------
// A : TMA 2D tensor load (2 UTMALDG/block, box [144 floats x 16 images]) +
//     pool (row-phase rotation) + circuit closed form + per-block partials.
// S : 1-block stats finalize -> g_sb.   C : pure normalize (1 float4/thread).
// ---------------------------------------------------------------------------

#define B_TOTAL 65536
#define IPB     32
#define NB      (B_TOTAL / IPB)         // 2048 blocks
#define THREADS 128
#define HALF_BYTES (16 * 576)           // 9216 per half-tile

__device__ __align__(16) float g_part[NB * 8];  // per-block [sum0..3, sumsq0..3]
__device__ __align__(16) float g_sb[8];         // scale[4], bias[4]

__device__ __forceinline__ void mbar_wait(unsigned int mb) {
    asm volatile(
        "{\n\t.reg .pred p;\n\t"
        "WAIT_%=:\n\t"
        "mbarrier.try_wait.parity.shared.b64 p, [%0], 0, 0x989680;\n\t"
        "@!p bra WAIT_%=;\n\t}"
        :: "r"(mb) : "memory");
}

__global__ __launch_bounds__(THREADS)
void qfc_kernelA(const __grid_constant__ CUtensorMap tmap,
                 const float* __restrict__ pr,
                 float* __restrict__ out)
{
    __shared__ __align__(128) float sd[IPB][144];   // 18,432 B (dense TMA rows)
    __shared__ __align__(8) unsigned long long mbar[2];
    __shared__ float swarp[4][8];

    const int tid  = threadIdx.x;
    const int wid  = tid >> 5;
    const int lane = tid & 31;
    const int g    = tid & 3;           // qubit index
    const int img  = tid >> 2;          // image within block (0..31)
    const long ib  = (long)blockIdx.x * IPB;

    unsigned int mb0 = (unsigned int)__cvta_generic_to_shared(&mbar[0]);
    unsigned int mb1 = (unsigned int)__cvta_generic_to_shared(&mbar[1]);

    if (tid == 0) {
        asm volatile("mbarrier.init.shared.b64 [%0], 1;" :: "r"(mb0) : "memory");
        asm volatile("mbarrier.init.shared.b64 [%0], 1;" :: "r"(mb1) : "memory");
        // make init visible to the async proxy before TMA completes on them
        asm volatile("fence.proxy.async.shared::cta;" ::: "memory");
    }
    __syncthreads();

    if (tid == 0) {
        const unsigned long long tm = (unsigned long long)&tmap;
        unsigned int d0 = (unsigned int)__cvta_generic_to_shared(&sd[0][0]);
        unsigned int d1 = (unsigned int)__cvta_generic_to_shared(&sd[16][0]);
        int y0 = (int)(ib);
        asm volatile("mbarrier.arrive.expect_tx.shared.b64 _, [%0], %1;"
                     :: "r"(mb0), "r"(HALF_BYTES) : "memory");
        asm volatile(
            "cp.async.bulk.tensor.2d.shared::cta.global.tile.mbarrier::complete_tx::bytes "
            "[%0], [%1, {%2, %3}], [%4];"
            :: "r"(d0), "l"(tm), "r"(0), "r"(y0), "r"(mb0) : "memory");
        asm volatile("mbarrier.arrive.expect_tx.shared.b64 _, [%0], %1;"
                     :: "r"(mb1), "r"(HALF_BYTES) : "memory");
        asm volatile(
            "cp.async.bulk.tensor.2d.shared::cta.global.tile.mbarrier::complete_tx::bytes "
            "[%0], [%1, {%2, %3}], [%4];"
            :: "r"(d1), "l"(tm), "r"(0), "r"(y0 + 16), "r"(mb1) : "memory");
    }

    const float phi  = pr[g * 2 + 0];
    const float lam  = pr[g * 2 + 1];
    const float clam = __cosf(lam);
    const float k2   = __sinf(lam) * __sinf(phi);

    float myz = 0.f;
    const int krot = (lane >> 3) & 3;   // row-phase rotation: caps conflicts at 2-way

    auto pool_z = [&]() {
        const float* base = &sd[img][g * 6];
        float a = 0.f;
#pragma unroll
        for (int rr = 0; rr < 6; rr++) {
            int r = rr + krot;
            r -= (r >= 6) ? 6 : 0;
            const float* row = base + r * 24;
            a += ((row[0] + row[1]) + (row[2] + row[3])) + (row[4] + row[5]);
        }
        const float theta = a * (1.f / 36.f);
        float st, ct;
        __sincosf(theta, &st, &ct);
        myz = clam * ct + k2 * st;
    };

    // half 0: images 0..15 (threads 0..63)
    mbar_wait(mb0);
    __syncthreads();
    if (tid < 64) pool_z();

    // half 1: images 16..31 (threads 64..127)
    mbar_wait(mb1);
    __syncthreads();
    if (tid >= 64) pool_z();

    // gather the 4 z's of this image (adjacent lanes)
    const unsigned lbase = lane & ~3u;
    const float z0 = __shfl_sync(0xffffffffu, myz, lbase + 0);
    const float z1 = __shfl_sync(0xffffffffu, myz, lbase + 1);
    const float z2 = __shfl_sync(0xffffffffu, myz, lbase + 2);
    const float z3 = __shfl_sync(0xffffffffu, myz, lbase + 3);

    float acc[8] = {0.f, 0.f, 0.f, 0.f, 0.f, 0.f, 0.f, 0.f};
    if (g == 0) {
        const float o0 = z0;
        const float o1 = o0 * z1;
        const float o2 = o1 * z2;
        const float o3 = o2 * z3;
        ((float4*)out)[ib + img] = make_float4(o0, o1, o2, o3);
        acc[0] = o0;      acc[1] = o1;      acc[2] = o2;      acc[3] = o3;
        acc[4] = o0 * o0; acc[5] = o1 * o1; acc[6] = o2 * o2; acc[7] = o3 * o3;
    }

    // warp reduction over lanes 0,4,..,28 then cross-warp combine
#pragma unroll
    for (int k = 0; k < 8; k++) {
#pragma unroll
        for (int off = 16; off >= 4; off >>= 1)
            acc[k] += __shfl_down_sync(0xffffffffu, acc[k], off);
    }
    if (lane == 0) {
#pragma unroll
        for (int k = 0; k < 8; k++) swarp[wid][k] = acc[k];
    }
    __syncthreads();
    if (tid < 8) {
        float r = swarp[0][tid] + swarp[1][tid] + swarp[2][tid] + swarp[3][tid];
        g_part[blockIdx.x * 8 + tid] = r;
    }
}

// ---- S: single-block stats finalize -> g_sb --------------------------------
__global__ __launch_bounds__(256)
void qfc_kernelS(const float* __restrict__ gamma,
                 const float* __restrict__ beta)
{
    __shared__ float swarp[8][8];
    const int tid  = threadIdx.x;
    const int wrp  = tid >> 5;
    const int lane = tid & 31;

    const float4* __restrict__ p4 = (const float4*)g_part;   // 4096 float4
    float r[8] = {0.f, 0.f, 0.f, 0.f, 0.f, 0.f, 0.f, 0.f};
#pragma unroll
    for (int it = 0; it < NB / 256; it++) {                   // 8 iters
        int j = tid + it * 256;
        float4 s  = __ldcg(&p4[j * 2]);
        float4 qq = __ldcg(&p4[j * 2 + 1]);
        r[0] += s.x;  r[1] += s.y;  r[2] += s.z;  r[3] += s.w;
        r[4] += qq.x; r[5] += qq.y; r[6] += qq.z; r[7] += qq.w;
    }
#pragma unroll
    for (int k = 0; k < 8; k++) {
#pragma unroll
        for (int off = 16; off; off >>= 1)
            r[k] += __shfl_down_sync(0xffffffffu, r[k], off);
    }
    if (lane == 0) {
#pragma unroll
        for (int k = 0; k < 8; k++) swarp[wrp][k] = r[k];
    }
    __syncthreads();

    if (tid < 4) {
        float ss = 0.f, qq = 0.f;
#pragma unroll
        for (int w = 0; w < 8; w++) { ss += swarp[w][tid]; qq += swarp[w][4 + tid]; }
        const float mean = ss * (1.f / (float)B_TOTAL);
        const float ex2  = qq * (1.f / (float)B_TOTAL);
        const float var  = fmaxf(ex2 - mean * mean, 0.f);
        const float inv  = rsqrtf(var + 1e-5f);
        const float sc   = gamma[tid] * inv;
        g_sb[tid]     = sc;
        g_sb[4 + tid] = beta[tid] - mean * sc;
    }
}

// ---- C: pure normalize, 1 float4 per thread --------------------------------
__global__ __launch_bounds__(256)
void qfc_kernelC(float* __restrict__ out)
{
    const float4 scv = *(const float4*)&g_sb[0];
    const float4 biv = *(const float4*)&g_sb[4];
    const int i = blockIdx.x * 256 + threadIdx.x;    // 65536 threads total
    float4 v = ((float4*)out)[i];
    v.x = v.x * scv.x + biv.x;
    v.y = v.y * scv.y + biv.y;
    v.z = v.z * scv.z + biv.z;
    v.w = v.w * scv.w + biv.w;
    ((float4*)out)[i] = v;
}

typedef CUresult (*PFN_encodeTiled)(
    CUtensorMap*, CUtensorMapDataType, cuuint32_t, void*,
    const cuuint64_t*, const cuuint64_t*, const cuuint32_t*, const cuuint32_t*,
    CUtensorMapInterleave, CUtensorMapSwizzle, CUtensorMapL2promotion,
    CUtensorMapFloatOOBfill);

extern "C" void kernel_launch(void* const* d_in, const int* in_sizes, int n_in,
                              void* d_out, int out_size)
{
    const float* x      = (const float*)d_in[0];   // [65536,1,24,24]
    const float* params = (const float*)d_in[1];   // [4,2]
    const float* gamma  = (const float*)d_in[2];   // [4]
    const float* beta   = (const float*)d_in[3];   // [4]
    float* out = (float*)d_out;                    // [65536,4]

    // host-side tensormap encode via driver entry point (no -lcuda needed)
    void* fn = nullptr;
    cudaDriverEntryPointQueryResult qres;
    cudaGetDriverEntryPointByVersion("cuTensorMapEncodeTiled", &fn, 12000,
                                     cudaEnableDefault, &qres);
    PFN_encodeTiled encode = (PFN_encodeTiled)fn;

    CUtensorMap tmap;
    cuuint64_t gdim[2]    = {144, (cuuint64_t)B_TOTAL};  // 144 floats x 65536 rows
    cuuint64_t gstride[1] = {2304};                      // bytes between rows
    cuuint32_t box[2]     = {144, 16};
    cuuint32_t estr[2]    = {1, 1};
    encode(&tmap, CU_TENSOR_MAP_DATA_TYPE_FLOAT32, 2, (void*)x,
           gdim, gstride, box, estr,
           CU_TENSOR_MAP_INTERLEAVE_NONE, CU_TENSOR_MAP_SWIZZLE_NONE,
           CU_TENSOR_MAP_L2_PROMOTION_L2_128B, CU_TENSOR_MAP_FLOAT_OOB_FILL_NONE);

    qfc_kernelA<<<NB, THREADS>>>(tmap, params, out);
    qfc_kernelS<<<1, 256>>>(gamma, beta);
    qfc_kernelC<<<B_TOTAL / 256, 256>>>(out);
}